// round 2
// baseline (speedup 1.0000x reference)
#include <cuda_runtime.h>
#include <cstdint>

// Problem constants (fixed by the dataset).
#define HIDDEN 128
#define MAX_NODES 100000
#define NODES_PER_BLOCK 16
#define NODES_PER_THREAD 8

// Scratch: per-node projections. p_src has b1 folded in.
__device__ float g_ps[MAX_NODES * HIDDEN];
__device__ float g_pd[MAX_NODES * HIDDEN];

// ---------------------------------------------------------------------------
// Phase 1: p_src[n][c] = sum_k z[n][k]*W1[k][c] + b1[c]
//          p_dst[n][c] = sum_k z[n][k]*W1[128+k][c]
// Block: 128 threads = 64 column-pairs x 2 node-groups (8 nodes each).
// Uses packed fp32x2 FMA (FFMA2) for 2x fp32 throughput.
// ---------------------------------------------------------------------------
__global__ void __launch_bounds__(128) proj_kernel(
    const float* __restrict__ z,
    const float* __restrict__ W1,
    const float* __restrict__ b1,
    int n_nodes)
{
    __shared__ float zs[NODES_PER_BLOCK][HIDDEN];

    const int node0 = blockIdx.x * NODES_PER_BLOCK;
    const int tid   = threadIdx.x;
    const int cpair = tid & 63;   // column pair: cols 2*cpair, 2*cpair+1
    const int grp   = tid >> 6;   // node group 0/1 (8 nodes each)

    // Cooperative, coalesced load of the z tile.
    #pragma unroll
    for (int i = 0; i < NODES_PER_BLOCK * HIDDEN / 128; i++) {
        int idx = tid + i * 128;
        int n = idx >> 7, k = idx & 127;
        int gn = node0 + n;
        zs[n][k] = (gn < n_nodes) ? z[(size_t)gn * HIDDEN + k] : 0.0f;
    }
    __syncthreads();

    unsigned long long acc_s[NODES_PER_THREAD];
    unsigned long long acc_d[NODES_PER_THREAD];
    #pragma unroll
    for (int n = 0; n < NODES_PER_THREAD; n++) { acc_s[n] = 0ull; acc_d[n] = 0ull; }

    const int nbase = grp * NODES_PER_THREAD;
    const unsigned long long* __restrict__ Wsrc =
        (const unsigned long long*)(W1) + cpair;                       // W1[k][2c..2c+1]
    const unsigned long long* __restrict__ Wdst =
        (const unsigned long long*)(W1 + HIDDEN * HIDDEN) + cpair;     // W1[128+k][..]

    #pragma unroll 8
    for (int k = 0; k < HIDDEN; k++) {
        unsigned long long ws = Wsrc[(size_t)k * (HIDDEN / 2)];
        unsigned long long wd = Wdst[(size_t)k * (HIDDEN / 2)];
        #pragma unroll
        for (int n = 0; n < NODES_PER_THREAD; n++) {
            unsigned int zi = __float_as_uint(zs[nbase + n][k]);
            unsigned long long zz;
            asm("mov.b64 %0, {%1, %1};" : "=l"(zz) : "r"(zi));
            asm("fma.rn.f32x2 %0, %1, %2, %0;" : "+l"(acc_s[n]) : "l"(zz), "l"(ws));
            asm("fma.rn.f32x2 %0, %1, %2, %0;" : "+l"(acc_d[n]) : "l"(zz), "l"(wd));
        }
    }

    // Fold b1 into the src projection.
    unsigned long long bb = *((const unsigned long long*)b1 + cpair);
    #pragma unroll
    for (int n = 0; n < NODES_PER_THREAD; n++) {
        asm("add.rn.f32x2 %0, %0, %1;" : "+l"(acc_s[n]) : "l"(bb));
    }

    #pragma unroll
    for (int n = 0; n < NODES_PER_THREAD; n++) {
        int gn = node0 + nbase + n;
        if (gn < n_nodes) {
            *((unsigned long long*)(g_ps + (size_t)gn * HIDDEN) + cpair) = acc_s[n];
            *((unsigned long long*)(g_pd + (size_t)gn * HIDDEN) + cpair) = acc_d[n];
        }
    }
}

// ---------------------------------------------------------------------------
// Phase 2: one warp per edge.
//   score[e] = sum_k relu(p_src[s][k] + p_dst[d][k]) * W2[k]  + b2
// Each lane handles 4 consecutive k via float4 (512B coalesced gather/warp).
// edge_index is INT32 (JAX x64 disabled -> int64 request materializes int32).
// ---------------------------------------------------------------------------
__global__ void __launch_bounds__(256) edge_kernel(
    const int* __restrict__ ei,         // [2, E] int32
    const float* __restrict__ W2,       // [128]
    const float* __restrict__ b2,       // [1]
    float* __restrict__ out,            // [E]
    int n_edges)
{
    int warp = (int)((blockIdx.x * (unsigned)blockDim.x + threadIdx.x) >> 5);
    int lane = threadIdx.x & 31;
    if (warp >= n_edges) return;

    int s = ei[warp];
    int d = ei[n_edges + warp];

    const float4 a = *((const float4*)(g_ps + (size_t)s * HIDDEN) + lane);
    const float4 b = *((const float4*)(g_pd + (size_t)d * HIDDEN) + lane);
    const float4 w = *((const float4*)W2 + lane);

    float h0 = fmaxf(a.x + b.x, 0.0f);
    float h1 = fmaxf(a.y + b.y, 0.0f);
    float h2 = fmaxf(a.z + b.z, 0.0f);
    float h3 = fmaxf(a.w + b.w, 0.0f);

    float acc = h0 * w.x;
    acc = fmaf(h1, w.y, acc);
    acc = fmaf(h2, w.z, acc);
    acc = fmaf(h3, w.w, acc);

    #pragma unroll
    for (int o = 16; o > 0; o >>= 1)
        acc += __shfl_xor_sync(0xFFFFFFFFu, acc, o);

    if (lane == 0) out[warp] = acc + b2[0];
}

// ---------------------------------------------------------------------------
// Launch
// Inputs (metadata order): 0 z[f32 N*128], 1 edge_index[i32 2*E],
//   2 W1[f32 256*128], 3 b1[f32 128], 4 W2[f32 128], 5 b2[f32 1]
// Output: f32 [E]
// ---------------------------------------------------------------------------
extern "C" void kernel_launch(void* const* d_in, const int* in_sizes, int n_in,
                              void* d_out, int out_size)
{
    const float* z  = (const float*)d_in[0];
    const int*   ei = (const int*)d_in[1];
    const float* W1 = (const float*)d_in[2];
    const float* b1 = (const float*)d_in[3];
    const float* W2 = (const float*)d_in[4];
    const float* b2 = (const float*)d_in[5];
    float*       out = (float*)d_out;

    int n_nodes = in_sizes[0] / HIDDEN;
    int n_edges = in_sizes[1] / 2;

    int pb = (n_nodes + NODES_PER_BLOCK - 1) / NODES_PER_BLOCK;
    proj_kernel<<<pb, 128>>>(z, W1, b1, n_nodes);

    // 8 warps (edges) per 256-thread block
    int eb = (n_edges + 7) / 8;
    edge_kernel<<<eb, 256>>>(ei, W2, b2, out, n_edges);
}

// round 3
// speedup vs baseline: 1.1862x; 1.1862x over previous
#include <cuda_runtime.h>
#include <cuda_fp16.h>
#include <cstdint>

// Problem constants (fixed by the dataset).
#define HIDDEN 128
#define MAX_NODES 100000
#define NODES_PER_BLOCK 16
#define NODES_PER_THREAD 8

// Scratch: per-node projections in fp16 (halves phase-2 gather traffic;
// both arrays = 51.2 MB -> L2-resident). p_src has b1 folded in.
__device__ __half g_psh[MAX_NODES * HIDDEN];
__device__ __half g_pdh[MAX_NODES * HIDDEN];

// ---------------------------------------------------------------------------
// Phase 1: p_src[n][c] = sum_k z[n][k]*W1[k][c] + b1[c]   (+ fp16 convert)
//          p_dst[n][c] = sum_k z[n][k]*W1[128+k][c]
// Block: 128 threads = 64 column-pairs x 2 node-groups (8 nodes each).
// z is staged in shared DUPLICATED as float2{z,z} so a single LDS.64 yields
// the packed multiplier for fma.rn.f32x2 (no per-FMA register packing).
// ---------------------------------------------------------------------------
__global__ void __launch_bounds__(128) proj_kernel(
    const float* __restrict__ z,
    const float* __restrict__ W1,
    const float* __restrict__ b1,
    int n_nodes)
{
    __shared__ float2 zs[NODES_PER_BLOCK][HIDDEN];   // 16 KB, {z,z} duplicated

    const int node0 = blockIdx.x * NODES_PER_BLOCK;
    const int tid   = threadIdx.x;
    const int cpair = tid & 63;   // column pair: cols 2*cpair, 2*cpair+1
    const int grp   = tid >> 6;   // node group 0/1 (8 nodes each)

    // Cooperative, coalesced load of the z tile (write duplicated).
    #pragma unroll
    for (int i = 0; i < NODES_PER_BLOCK * HIDDEN / 128; i++) {
        int idx = tid + i * 128;
        int n = idx >> 7, k = idx & 127;
        int gn = node0 + n;
        float v = (gn < n_nodes) ? z[(size_t)gn * HIDDEN + k] : 0.0f;
        zs[n][k] = make_float2(v, v);
    }
    __syncthreads();

    unsigned long long acc_s[NODES_PER_THREAD];
    unsigned long long acc_d[NODES_PER_THREAD];
    #pragma unroll
    for (int n = 0; n < NODES_PER_THREAD; n++) { acc_s[n] = 0ull; acc_d[n] = 0ull; }

    const int nbase = grp * NODES_PER_THREAD;
    const unsigned long long* __restrict__ Wsrc =
        (const unsigned long long*)(W1) + cpair;                       // W1[k][2c..2c+1]
    const unsigned long long* __restrict__ Wdst =
        (const unsigned long long*)(W1 + HIDDEN * HIDDEN) + cpair;     // W1[128+k][..]

    #pragma unroll 8
    for (int k = 0; k < HIDDEN; k++) {
        unsigned long long ws = Wsrc[(size_t)k * (HIDDEN / 2)];
        unsigned long long wd = Wdst[(size_t)k * (HIDDEN / 2)];
        #pragma unroll
        for (int n = 0; n < NODES_PER_THREAD; n++) {
            unsigned long long zz = *(const unsigned long long*)&zs[nbase + n][k];
            asm("fma.rn.f32x2 %0, %1, %2, %0;" : "+l"(acc_s[n]) : "l"(zz), "l"(ws));
            asm("fma.rn.f32x2 %0, %1, %2, %0;" : "+l"(acc_d[n]) : "l"(zz), "l"(wd));
        }
    }

    // Fold b1 into the src projection.
    unsigned long long bb = *((const unsigned long long*)b1 + cpair);
    #pragma unroll
    for (int n = 0; n < NODES_PER_THREAD; n++) {
        asm("add.rn.f32x2 %0, %0, %1;" : "+l"(acc_s[n]) : "l"(bb));
    }

    // Convert to fp16 and store.
    #pragma unroll
    for (int n = 0; n < NODES_PER_THREAD; n++) {
        int gn = node0 + nbase + n;
        if (gn < n_nodes) {
            float2 fs = *(float2*)&acc_s[n];
            float2 fd = *(float2*)&acc_d[n];
            ((__half2*)(g_psh + (size_t)gn * HIDDEN))[cpair] = __float22half2_rn(fs);
            ((__half2*)(g_pdh + (size_t)gn * HIDDEN))[cpair] = __float22half2_rn(fd);
        }
    }
}

// ---------------------------------------------------------------------------
// Phase 2: one warp per TWO edges (4 independent 8B gathers in flight/lane).
//   score[e] = sum_k relu(p_src[s][k] + p_dst[d][k]) * W2[k] + b2
// Each lane handles 4 consecutive k (4 halves = 8B) per edge; 256B
// coalesced per warp per gathered row.
// ---------------------------------------------------------------------------
__global__ void __launch_bounds__(256) edge_kernel(
    const int* __restrict__ ei,         // [2, E] int32
    const float* __restrict__ W2,       // [128]
    const float* __restrict__ b2,       // [1]
    float* __restrict__ out,            // [E]
    int n_edges)
{
    int warp = (int)((blockIdx.x * (unsigned)blockDim.x + threadIdx.x) >> 5);
    int lane = threadIdx.x & 31;
    int e0 = warp * 2;
    if (e0 >= n_edges) return;
    int e1 = e0 + 1;
    bool has1 = (e1 < n_edges);

    int s0 = ei[e0];
    int d0 = ei[n_edges + e0];
    int s1 = has1 ? ei[e1] : s0;
    int d1 = has1 ? ei[n_edges + e1] : d0;

    // 4 independent gathers (8B each, coalesced 256B/warp).
    const uint2 ra0 = *((const uint2*)g_psh + (size_t)s0 * (HIDDEN / 4) + lane);
    const uint2 rb0 = *((const uint2*)g_pdh + (size_t)d0 * (HIDDEN / 4) + lane);
    const uint2 ra1 = *((const uint2*)g_psh + (size_t)s1 * (HIDDEN / 4) + lane);
    const uint2 rb1 = *((const uint2*)g_pdh + (size_t)d1 * (HIDDEN / 4) + lane);

    const float4 w = *((const float4*)W2 + lane);

    float2 a01, a23, b01, b23;
    float acc0, acc1;

    // edge 0
    a01 = __half22float2(*(const __half2*)&ra0.x);
    a23 = __half22float2(*(const __half2*)&ra0.y);
    b01 = __half22float2(*(const __half2*)&rb0.x);
    b23 = __half22float2(*(const __half2*)&rb0.y);
    acc0 =        fmaxf(a01.x + b01.x, 0.0f) * w.x;
    acc0 = fmaf(fmaxf(a01.y + b01.y, 0.0f), w.y, acc0);
    acc0 = fmaf(fmaxf(a23.x + b23.x, 0.0f), w.z, acc0);
    acc0 = fmaf(fmaxf(a23.y + b23.y, 0.0f), w.w, acc0);

    // edge 1
    a01 = __half22float2(*(const __half2*)&ra1.x);
    a23 = __half22float2(*(const __half2*)&ra1.y);
    b01 = __half22float2(*(const __half2*)&rb1.x);
    b23 = __half22float2(*(const __half2*)&rb1.y);
    acc1 =        fmaxf(a01.x + b01.x, 0.0f) * w.x;
    acc1 = fmaf(fmaxf(a01.y + b01.y, 0.0f), w.y, acc1);
    acc1 = fmaf(fmaxf(a23.x + b23.x, 0.0f), w.z, acc1);
    acc1 = fmaf(fmaxf(a23.y + b23.y, 0.0f), w.w, acc1);

    #pragma unroll
    for (int o = 16; o > 0; o >>= 1) {
        acc0 += __shfl_xor_sync(0xFFFFFFFFu, acc0, o);
        acc1 += __shfl_xor_sync(0xFFFFFFFFu, acc1, o);
    }

    if (lane == 0) {
        float bb = b2[0];
        out[e0] = acc0 + bb;
        if (has1) out[e1] = acc1 + bb;
    }
}

// ---------------------------------------------------------------------------
// Launch
// Inputs (metadata order): 0 z[f32 N*128], 1 edge_index[i32 2*E],
//   2 W1[f32 256*128], 3 b1[f32 128], 4 W2[f32 128], 5 b2[f32 1]
// Output: f32 [E]
// ---------------------------------------------------------------------------
extern "C" void kernel_launch(void* const* d_in, const int* in_sizes, int n_in,
                              void* d_out, int out_size)
{
    const float* z  = (const float*)d_in[0];
    const int*   ei = (const int*)d_in[1];
    const float* W1 = (const float*)d_in[2];
    const float* b1 = (const float*)d_in[3];
    const float* W2 = (const float*)d_in[4];
    const float* b2 = (const float*)d_in[5];
    float*       out = (float*)d_out;

    int n_nodes = in_sizes[0] / HIDDEN;
    int n_edges = in_sizes[1] / 2;

    int pb = (n_nodes + NODES_PER_BLOCK - 1) / NODES_PER_BLOCK;
    proj_kernel<<<pb, 128>>>(z, W1, b1, n_nodes);

    // 2 edges per warp, 8 warps per 256-thread block -> 16 edges/block
    int eb = (n_edges + 15) / 16;
    edge_kernel<<<eb, 256>>>(ei, W2, b2, out, n_edges);
}

// round 5
// speedup vs baseline: 2.2216x; 1.8729x over previous
#include <cuda_runtime.h>
#include <cuda_fp16.h>
#include <cstdint>

#define HIDDEN 128
#define MAX_NODES 100000
#define NODES_PER_CTA 64
#define PROJ_THREADS 256

// Interleaved per-node projections, fp16: row = [src-proj(+b1) | dst-proj].
__device__ __half g_p[(size_t)MAX_NODES * 256];

__device__ __forceinline__ uint32_t smem_u32(const void* p) {
    uint32_t a;
    asm("{ .reg .u64 t; cvta.to.shared.u64 t, %1; cvt.u32.u64 %0, t; }"
        : "=r"(a) : "l"(p));
    return a;
}

// SMEM layout (dynamic, 82432 B -> 2 CTAs/SM):
//   [0,512)        b1 (128 f32)
//   [512,16896)    A: z fp16, 64 rows x 256B, XOR-16B swizzle
//   [16896,82432)  B: W1^T fp16, 256 rows x 256B, XOR-16B swizzle
//                  (reused after MMA as OUT: 64 rows x 528B)
#define SM_B1  0
#define SM_A   512
#define SM_B   16896
#define SM_OUT SM_B
#define SMEM_BYTES 82432

__global__ void __launch_bounds__(PROJ_THREADS, 2)
proj_mma_kernel(const float* __restrict__ z,
                const float* __restrict__ W1,
                const float* __restrict__ b1,
                int n_nodes)
{
    extern __shared__ char smem[];
    const uint32_t smem_base = smem_u32(smem);
    const int tid  = threadIdx.x;
    const int lane = tid & 31;
    const int wid  = tid >> 5;
    const int node0 = blockIdx.x * NODES_PER_CTA;

    // ---- stage b1 ----
    if (tid < 128) ((float*)(smem + SM_B1))[tid] = b1[tid];

    // ---- stage A: z[node0..node0+63][0..127] -> fp16 swizzled ----
    #pragma unroll
    for (int i = 0; i < 8; i++) {
        int chunk = tid + i * 256;              // 2048 float4-chunks
        int row = chunk >> 5, c4 = chunk & 31;  // 32 float4 per row
        int gn = node0 + row;
        float4 f = make_float4(0.f, 0.f, 0.f, 0.f);
        if (gn < n_nodes) f = ((const float4*)(z + (size_t)gn * HIDDEN))[c4];
        __half2 h01 = __floats2half2_rn(f.x, f.y);
        __half2 h23 = __floats2half2_rn(f.z, f.w);
        uint2 v;
        v.x = *(uint32_t*)&h01;
        v.y = *(uint32_t*)&h23;
        uint32_t off = ((uint32_t)(c4 * 8)) ^ ((uint32_t)(row & 7) << 4);
        *(uint2*)(smem + SM_A + row * 256 + off) = v;
    }

    // ---- stage B: B[n][k] = W1[k][n] (n<128) / W1[128+k][n-128] ----
    {
        int n = tid;                       // one n-row per thread
        int c = n & 127;
        int rbase = (n < 128) ? 0 : 128;
        #pragma unroll 4
        for (int kc = 0; kc < 32; kc++) {  // 4 k per iter
            float f0 = W1[(size_t)(rbase + kc * 4 + 0) * 128 + c];
            float f1 = W1[(size_t)(rbase + kc * 4 + 1) * 128 + c];
            float f2 = W1[(size_t)(rbase + kc * 4 + 2) * 128 + c];
            float f3 = W1[(size_t)(rbase + kc * 4 + 3) * 128 + c];
            __half2 h01 = __floats2half2_rn(f0, f1);
            __half2 h23 = __floats2half2_rn(f2, f3);
            uint2 v;
            v.x = *(uint32_t*)&h01;
            v.y = *(uint32_t*)&h23;
            uint32_t off = ((uint32_t)(kc * 8)) ^ ((uint32_t)(n & 7) << 4);
            *(uint2*)(smem + SM_B + n * 256 + off) = v;
        }
    }
    __syncthreads();

    // ---- MMA mainloop: warp grid 2(m) x 4(n); warp tile 32 x 64 ----
    const int wm = wid >> 2;    // rows 32*wm
    const int wn = wid & 3;     // cols 64*wn
    float acc[2][8][4];
    #pragma unroll
    for (int mi = 0; mi < 2; mi++)
        #pragma unroll
        for (int nj = 0; nj < 8; nj++)
            #pragma unroll
            for (int q = 0; q < 4; q++) acc[mi][nj][q] = 0.0f;

    const uint32_t smA = smem_base + SM_A;
    const uint32_t smB = smem_base + SM_B;

    #pragma unroll
    for (int ks = 0; ks < 8; ks++) {
        uint32_t a[2][4];
        #pragma unroll
        for (int mi = 0; mi < 2; mi++) {
            int r = wm * 32 + mi * 16 + (lane & 15);
            uint32_t kb = (uint32_t)(ks * 32 + ((lane >> 4) << 4));
            uint32_t addr = smA + (uint32_t)(r * 256) + (kb ^ ((uint32_t)(r & 7) << 4));
            asm volatile("ldmatrix.sync.aligned.m8n8.x4.shared.b16 {%0,%1,%2,%3}, [%4];"
                         : "=r"(a[mi][0]), "=r"(a[mi][1]), "=r"(a[mi][2]), "=r"(a[mi][3])
                         : "r"(addr));
        }
        uint32_t b[8][2];
        #pragma unroll
        for (int nj = 0; nj < 8; nj++) {
            int r = wn * 64 + nj * 8 + (lane & 7);
            uint32_t kb = (uint32_t)(ks * 32 + (((lane >> 3) & 1) << 4));
            uint32_t addr = smB + (uint32_t)(r * 256) + (kb ^ ((uint32_t)(r & 7) << 4));
            asm volatile("ldmatrix.sync.aligned.m8n8.x2.shared.b16 {%0,%1}, [%2];"
                         : "=r"(b[nj][0]), "=r"(b[nj][1]) : "r"(addr));
        }
        #pragma unroll
        for (int mi = 0; mi < 2; mi++)
            #pragma unroll
            for (int nj = 0; nj < 8; nj++) {
                asm volatile(
                    "mma.sync.aligned.m16n8k16.row.col.f32.f16.f16.f32 "
                    "{%0,%1,%2,%3}, {%4,%5,%6,%7}, {%8,%9}, {%0,%1,%2,%3};"
                    : "+f"(acc[mi][nj][0]), "+f"(acc[mi][nj][1]),
                      "+f"(acc[mi][nj][2]), "+f"(acc[mi][nj][3])
                    : "r"(a[mi][0]), "r"(a[mi][1]), "r"(a[mi][2]), "r"(a[mi][3]),
                      "r"(b[nj][0]), "r"(b[nj][1]));
            }
    }
    __syncthreads();   // all ldmatrix reads of SM_B done before OUT overwrite

    // ---- epilogue: +b1 (cols<128), fp16, stage to SMEM (row stride 528) ----
    #pragma unroll
    for (int mi = 0; mi < 2; mi++) {
        #pragma unroll
        for (int nj = 0; nj < 8; nj++) {
            int row = wm * 32 + mi * 16 + (lane >> 2);
            int col = wn * 64 + nj * 8 + ((lane & 3) << 1);
            float bx = 0.f, by = 0.f;
            if (col < 128) {
                float2 bb = *(const float2*)(smem + SM_B1 + col * 4);
                bx = bb.x; by = bb.y;
            }
            __half2 v0 = __floats2half2_rn(acc[mi][nj][0] + bx, acc[mi][nj][1] + by);
            __half2 v1 = __floats2half2_rn(acc[mi][nj][2] + bx, acc[mi][nj][3] + by);
            *(__half2*)(smem + SM_OUT + row * 528 + col * 2) = v0;
            *(__half2*)(smem + SM_OUT + (row + 8) * 528 + col * 2) = v1;
        }
    }
    __syncthreads();

    // ---- coalesced write-out: 64 rows x 512B -> g_p ----
    #pragma unroll
    for (int i = 0; i < 8; i++) {
        int chunk = tid + i * 256;              // 2048 16B-chunks
        int row = chunk >> 5, c16 = chunk & 31;
        int gn = node0 + row;
        if (gn < n_nodes) {
            uint4 v = *(const uint4*)(smem + SM_OUT + row * 528 + c16 * 16);
            ((uint4*)(g_p + (size_t)gn * 256))[c16] = v;
        }
    }
}

// ---------------------------------------------------------------------------
// Phase 2: one warp per TWO edges (R3 form, interleaved g_p).
// ---------------------------------------------------------------------------
__global__ void __launch_bounds__(256) edge_kernel(
    const int* __restrict__ ei,
    const float* __restrict__ W2,
    const float* __restrict__ b2,
    float* __restrict__ out,
    int n_edges)
{
    int warp = (int)((blockIdx.x * (unsigned)blockDim.x + threadIdx.x) >> 5);
    int lane = threadIdx.x & 31;
    int e0 = warp * 2;
    if (e0 >= n_edges) return;
    int e1 = e0 + 1;
    bool has1 = (e1 < n_edges);

    int s0 = ei[e0];
    int d0 = ei[n_edges + e0];
    int s1 = has1 ? ei[e1] : s0;
    int d1 = has1 ? ei[n_edges + e1] : d0;

    const uint2 ra0 = *((const uint2*)(g_p + (size_t)s0 * 256) + lane);
    const uint2 rb0 = *((const uint2*)(g_p + (size_t)d0 * 256 + 128) + lane);
    const uint2 ra1 = *((const uint2*)(g_p + (size_t)s1 * 256) + lane);
    const uint2 rb1 = *((const uint2*)(g_p + (size_t)d1 * 256 + 128) + lane);

    const float4 w = *((const float4*)W2 + lane);

    float2 a01, a23, b01, b23;
    float acc0, acc1;

    a01 = __half22float2(*(const __half2*)&ra0.x);
    a23 = __half22float2(*(const __half2*)&ra0.y);
    b01 = __half22float2(*(const __half2*)&rb0.x);
    b23 = __half22float2(*(const __half2*)&rb0.y);
    acc0 =      fmaxf(a01.x + b01.x, 0.0f) * w.x;
    acc0 = fmaf(fmaxf(a01.y + b01.y, 0.0f), w.y, acc0);
    acc0 = fmaf(fmaxf(a23.x + b23.x, 0.0f), w.z, acc0);
    acc0 = fmaf(fmaxf(a23.y + b23.y, 0.0f), w.w, acc0);

    a01 = __half22float2(*(const __half2*)&ra1.x);
    a23 = __half22float2(*(const __half2*)&ra1.y);
    b01 = __half22float2(*(const __half2*)&rb1.x);
    b23 = __half22float2(*(const __half2*)&rb1.y);
    acc1 =      fmaxf(a01.x + b01.x, 0.0f) * w.x;
    acc1 = fmaf(fmaxf(a01.y + b01.y, 0.0f), w.y, acc1);
    acc1 = fmaf(fmaxf(a23.x + b23.x, 0.0f), w.z, acc1);
    acc1 = fmaf(fmaxf(a23.y + b23.y, 0.0f), w.w, acc1);

    #pragma unroll
    for (int o = 16; o > 0; o >>= 1) {
        acc0 += __shfl_xor_sync(0xFFFFFFFFu, acc0, o);
        acc1 += __shfl_xor_sync(0xFFFFFFFFu, acc1, o);
    }

    if (lane == 0) {
        float bb = b2[0];
        out[e0] = acc0 + bb;
        if (has1) out[e1] = acc1 + bb;
    }
}

// ---------------------------------------------------------------------------
// Launch
// Inputs: 0 z[f32 N*128], 1 edge_index[i32 2*E], 2 W1[f32 256*128],
//         3 b1[f32 128], 4 W2[f32 128], 5 b2[f32 1]; out f32 [E].
// ---------------------------------------------------------------------------
extern "C" void kernel_launch(void* const* d_in, const int* in_sizes, int n_in,
                              void* d_out, int out_size)
{
    const float* z  = (const float*)d_in[0];
    const int*   ei = (const int*)d_in[1];
    const float* W1 = (const float*)d_in[2];
    const float* b1 = (const float*)d_in[3];
    const float* W2 = (const float*)d_in[4];
    const float* b2 = (const float*)d_in[5];
    float*       out = (float*)d_out;

    int n_nodes = in_sizes[0] / HIDDEN;
    int n_edges = in_sizes[1] / 2;

    cudaFuncSetAttribute(proj_mma_kernel,
                         cudaFuncAttributeMaxDynamicSharedMemorySize, SMEM_BYTES);

    int pb = (n_nodes + NODES_PER_CTA - 1) / NODES_PER_CTA;
    proj_mma_kernel<<<pb, PROJ_THREADS, SMEM_BYTES>>>(z, W1, b1, n_nodes);

    int eb = (n_edges + 15) / 16;
    edge_kernel<<<eb, 256>>>(ei, W2, b2, out, n_edges);
}

// round 6
// speedup vs baseline: 2.4394x; 1.0980x over previous
#include <cuda_runtime.h>
#include <cuda_fp16.h>
#include <cstdint>

#define HIDDEN 128
#define MAX_NODES 100000
#define NODES_PER_CTA 64
#define PROJ_THREADS 256

// Interleaved per-node projections, fp16: row = [src-proj(+b1) | dst-proj].
__device__ __half g_p[(size_t)MAX_NODES * 256];

__device__ __forceinline__ uint32_t smem_u32(const void* p) {
    uint32_t a;
    asm("{ .reg .u64 t; cvta.to.shared.u64 t, %1; cvt.u32.u64 %0, t; }"
        : "=r"(a) : "l"(p));
    return a;
}

// SMEM layout (dynamic, 82432 B -> 2 CTAs/SM):
//   [0,512)        b1 (128 f32)
//   [512,16896)    A: z fp16, 64 rows x 256B, XOR-16B swizzle   (per tile)
//   [16896,82432)  B: W1^T fp16, 256 rows x 256B, XOR-16B swizzle (persistent)
#define SM_B1  0
#define SM_A   512
#define SM_B   16896
#define SMEM_BYTES 82432

// ---------------------------------------------------------------------------
// Phase 1: persistent-CTA fp16 tensor-core projection.
//   D[64 x 256] = z_tile[64 x 128] @ B[128 x 256], B[n][k] = W1^T
// Each CTA stages B ONCE, then loops over node tiles (grid-strided).
// Epilogue adds b1 (cols<128) and stores half2 directly from registers.
// ---------------------------------------------------------------------------
__global__ void __launch_bounds__(PROJ_THREADS, 2)
proj_mma_kernel(const float* __restrict__ z,
                const float* __restrict__ W1,
                const float* __restrict__ b1,
                int n_nodes, int n_tiles)
{
    extern __shared__ char smem[];
    const uint32_t smem_base = smem_u32(smem);
    const int tid  = threadIdx.x;
    const int lane = tid & 31;
    const int wid  = tid >> 5;
    const int wm = wid >> 2;    // warp row  (2)
    const int wn = wid & 3;     // warp col  (4)

    // ---- stage b1 ----
    if (tid < 128) ((float*)(smem + SM_B1))[tid] = b1[tid];

    // ---- stage B once: B[n][k] = W1[k][n] (n<128) / W1[128+k][n-128] ----
    {
        int n = tid;
        int c = n & 127;
        int rbase = (n < 128) ? 0 : 128;
        #pragma unroll 4
        for (int kc = 0; kc < 32; kc++) {
            float f0 = W1[(size_t)(rbase + kc * 4 + 0) * 128 + c];
            float f1 = W1[(size_t)(rbase + kc * 4 + 1) * 128 + c];
            float f2 = W1[(size_t)(rbase + kc * 4 + 2) * 128 + c];
            float f3 = W1[(size_t)(rbase + kc * 4 + 3) * 128 + c];
            __half2 h01 = __floats2half2_rn(f0, f1);
            __half2 h23 = __floats2half2_rn(f2, f3);
            uint2 v;
            v.x = *(uint32_t*)&h01;
            v.y = *(uint32_t*)&h23;
            uint32_t off = ((uint32_t)(kc * 8)) ^ ((uint32_t)(n & 7) << 4);
            *(uint2*)(smem + SM_B + n * 256 + off) = v;
        }
    }
    __syncthreads();

    // ---- per-thread bias pairs (fixed columns across tiles) ----
    float bx[8], by[8];
    #pragma unroll
    for (int nj = 0; nj < 8; nj++) {
        int col = wn * 64 + nj * 8 + ((lane & 3) << 1);
        if (col < 128) {
            float2 bb = *(const float2*)(smem + SM_B1 + col * 4);
            bx[nj] = bb.x; by[nj] = bb.y;
        } else {
            bx[nj] = 0.f; by[nj] = 0.f;
        }
    }

    const uint32_t smA = smem_base + SM_A;
    const uint32_t smB = smem_base + SM_B;

    for (int tile = blockIdx.x; tile < n_tiles; tile += gridDim.x) {
        const int node0 = tile * NODES_PER_CTA;

        // ---- stage A: z[node0..node0+63][:] -> fp16 swizzled ----
        #pragma unroll
        for (int i = 0; i < 8; i++) {
            int chunk = tid + i * 256;              // 2048 float4-chunks
            int row = chunk >> 5, c4 = chunk & 31;
            int gn = node0 + row;
            float4 f = make_float4(0.f, 0.f, 0.f, 0.f);
            if (gn < n_nodes) f = ((const float4*)(z + (size_t)gn * HIDDEN))[c4];
            __half2 h01 = __floats2half2_rn(f.x, f.y);
            __half2 h23 = __floats2half2_rn(f.z, f.w);
            uint2 v;
            v.x = *(uint32_t*)&h01;
            v.y = *(uint32_t*)&h23;
            uint32_t off = ((uint32_t)(c4 * 8)) ^ ((uint32_t)(row & 7) << 4);
            *(uint2*)(smem + SM_A + row * 256 + off) = v;
        }
        __syncthreads();

        // ---- MMA mainloop: warp tile 32 x 64 ----
        float acc[2][8][4];
        #pragma unroll
        for (int mi = 0; mi < 2; mi++)
            #pragma unroll
            for (int nj = 0; nj < 8; nj++)
                #pragma unroll
                for (int q = 0; q < 4; q++) acc[mi][nj][q] = 0.0f;

        #pragma unroll
        for (int ks = 0; ks < 8; ks++) {
            uint32_t a[2][4];
            #pragma unroll
            for (int mi = 0; mi < 2; mi++) {
                int r = wm * 32 + mi * 16 + (lane & 15);
                uint32_t kb = (uint32_t)(ks * 32 + ((lane >> 4) << 4));
                uint32_t addr = smA + (uint32_t)(r * 256) + (kb ^ ((uint32_t)(r & 7) << 4));
                asm volatile("ldmatrix.sync.aligned.m8n8.x4.shared.b16 {%0,%1,%2,%3}, [%4];"
                             : "=r"(a[mi][0]), "=r"(a[mi][1]), "=r"(a[mi][2]), "=r"(a[mi][3])
                             : "r"(addr));
            }
            uint32_t b[8][2];
            #pragma unroll
            for (int nj = 0; nj < 8; nj++) {
                int r = wn * 64 + nj * 8 + (lane & 7);
                uint32_t kb = (uint32_t)(ks * 32 + (((lane >> 3) & 1) << 4));
                uint32_t addr = smB + (uint32_t)(r * 256) + (kb ^ ((uint32_t)(r & 7) << 4));
                asm volatile("ldmatrix.sync.aligned.m8n8.x2.shared.b16 {%0,%1}, [%2];"
                             : "=r"(b[nj][0]), "=r"(b[nj][1]) : "r"(addr));
            }
            #pragma unroll
            for (int mi = 0; mi < 2; mi++)
                #pragma unroll
                for (int nj = 0; nj < 8; nj++) {
                    asm volatile(
                        "mma.sync.aligned.m16n8k16.row.col.f32.f16.f16.f32 "
                        "{%0,%1,%2,%3}, {%4,%5,%6,%7}, {%8,%9}, {%0,%1,%2,%3};"
                        : "+f"(acc[mi][nj][0]), "+f"(acc[mi][nj][1]),
                          "+f"(acc[mi][nj][2]), "+f"(acc[mi][nj][3])
                        : "r"(a[mi][0]), "r"(a[mi][1]), "r"(a[mi][2]), "r"(a[mi][3]),
                          "r"(b[nj][0]), "r"(b[nj][1]));
                }
        }
        __syncthreads();   // SM_A consumed; safe to overwrite next tile

        // ---- epilogue: +bias, fp16, direct register stores ----
        #pragma unroll
        for (int mi = 0; mi < 2; mi++) {
            int row = wm * 32 + mi * 16 + (lane >> 2);
            int gn0 = node0 + row;
            int gn1 = gn0 + 8;
            #pragma unroll
            for (int nj = 0; nj < 8; nj++) {
                int col = wn * 64 + nj * 8 + ((lane & 3) << 1);
                __half2 v0 = __floats2half2_rn(acc[mi][nj][0] + bx[nj],
                                               acc[mi][nj][1] + by[nj]);
                __half2 v1 = __floats2half2_rn(acc[mi][nj][2] + bx[nj],
                                               acc[mi][nj][3] + by[nj]);
                if (gn0 < n_nodes) *(__half2*)(g_p + (size_t)gn0 * 256 + col) = v0;
                if (gn1 < n_nodes) *(__half2*)(g_p + (size_t)gn1 * 256 + col) = v1;
            }
        }
    }
}

// ---------------------------------------------------------------------------
// Phase 2: half-warp per edge (2 edges/warp).
// Lane kl=lane&15 covers 8 k (one 16B load per row). fp16 add+relu,
// fp32 dot with W2, 4-stage butterfly within the half-warp.
// ---------------------------------------------------------------------------
__global__ void __launch_bounds__(256) edge_kernel(
    const int* __restrict__ ei,
    const float* __restrict__ W2,
    const float* __restrict__ b2,
    float* __restrict__ out,
    int n_edges)
{
    int warp = (int)((blockIdx.x * (unsigned)blockDim.x + threadIdx.x) >> 5);
    int lane = threadIdx.x & 31;
    int e0 = warp * 2;
    if (e0 >= n_edges) return;

    int eh = e0 + (lane >> 4);
    int el = (eh < n_edges) ? eh : e0;
    int s = ei[el];
    int d = ei[n_edges + el];
    int kl = lane & 15;

    const uint4 ra = *(const uint4*)(g_p + (size_t)s * 256 + kl * 8);
    const uint4 rb = *(const uint4*)(g_p + (size_t)d * 256 + 128 + kl * 8);
    const float4 w0 = *((const float4*)W2 + kl * 2);
    const float4 w1 = *((const float4*)W2 + kl * 2 + 1);

    const __half2 z2 = __float2half2_rn(0.0f);
    __half2 h0 = __hmax2(__hadd2(*(const __half2*)&ra.x, *(const __half2*)&rb.x), z2);
    __half2 h1 = __hmax2(__hadd2(*(const __half2*)&ra.y, *(const __half2*)&rb.y), z2);
    __half2 h2 = __hmax2(__hadd2(*(const __half2*)&ra.z, *(const __half2*)&rb.z), z2);
    __half2 h3 = __hmax2(__hadd2(*(const __half2*)&ra.w, *(const __half2*)&rb.w), z2);

    float2 f0 = __half22float2(h0);
    float2 f1 = __half22float2(h1);
    float2 f2 = __half22float2(h2);
    float2 f3 = __half22float2(h3);

    float acc =       f0.x * w0.x;
    acc = fmaf(f0.y, w0.y, acc);
    acc = fmaf(f1.x, w0.z, acc);
    acc = fmaf(f1.y, w0.w, acc);
    acc = fmaf(f2.x, w1.x, acc);
    acc = fmaf(f2.y, w1.y, acc);
    acc = fmaf(f3.x, w1.z, acc);
    acc = fmaf(f3.y, w1.w, acc);

    #pragma unroll
    for (int o = 8; o > 0; o >>= 1)
        acc += __shfl_xor_sync(0xFFFFFFFFu, acc, o);

    if (kl == 0 && eh < n_edges) out[eh] = acc + b2[0];
}

// ---------------------------------------------------------------------------
// Launch
// Inputs: 0 z[f32 N*128], 1 edge_index[i32 2*E], 2 W1[f32 256*128],
//         3 b1[f32 128], 4 W2[f32 128], 5 b2[f32 1]; out f32 [E].
// ---------------------------------------------------------------------------
extern "C" void kernel_launch(void* const* d_in, const int* in_sizes, int n_in,
                              void* d_out, int out_size)
{
    const float* z  = (const float*)d_in[0];
    const int*   ei = (const int*)d_in[1];
    const float* W1 = (const float*)d_in[2];
    const float* b1 = (const float*)d_in[3];
    const float* W2 = (const float*)d_in[4];
    const float* b2 = (const float*)d_in[5];
    float*       out = (float*)d_out;

    int n_nodes = in_sizes[0] / HIDDEN;
    int n_edges = in_sizes[1] / 2;
    int n_tiles = (n_nodes + NODES_PER_CTA - 1) / NODES_PER_CTA;

    cudaFuncSetAttribute(proj_mma_kernel,
                         cudaFuncAttributeMaxDynamicSharedMemorySize, SMEM_BYTES);

    int pg = 2 * 148;                 // persistent: 2 CTAs per SM
    if (pg > n_tiles) pg = n_tiles;
    proj_mma_kernel<<<pg, PROJ_THREADS, SMEM_BYTES>>>(z, W1, b1, n_nodes, n_tiles);

    int eb = (n_edges + 15) / 16;     // 16 edges per 256-thread block
    edge_kernel<<<eb, 256>>>(ei, W2, b2, out, n_edges);
}

// round 7
// speedup vs baseline: 3.1816x; 1.3043x over previous
#include <cuda_runtime.h>
#include <cuda_fp16.h>
#include <cstdint>

#define HIDDEN 128
#define MAX_NODES 100000
#define NODES_PER_CTA 64
#define PROJ_THREADS 256

// Interleaved per-node projections, fp16: row = [src-proj(+b1) | dst-proj].
__device__ __half g_p[(size_t)MAX_NODES * 256];

__device__ __forceinline__ uint32_t smem_u32(const void* p) {
    uint32_t a;
    asm("{ .reg .u64 t; cvta.to.shared.u64 t, %1; cvt.u32.u64 %0, t; }"
        : "=r"(a) : "l"(p));
    return a;
}

// SMEM layout (dynamic, 82432 B -> 2 CTAs/SM):
//   [0,512)        b1 (128 f32)
//   [512,16896)    A: z fp16, 64 rows x 256B, XOR-16B swizzle   (per tile)
//   [16896,82432)  B: W1^T fp16, 256 rows x 256B, XOR-16B swizzle (persistent)
#define SM_B1  0
#define SM_A   512
#define SM_B   16896
#define SMEM_BYTES 82432

// ---------------------------------------------------------------------------
// Phase 1: persistent-CTA fp16 tensor-core projection (unchanged from R6).
// ---------------------------------------------------------------------------
__global__ void __launch_bounds__(PROJ_THREADS, 2)
proj_mma_kernel(const float* __restrict__ z,
                const float* __restrict__ W1,
                const float* __restrict__ b1,
                int n_nodes, int n_tiles)
{
    extern __shared__ char smem[];
    const uint32_t smem_base = smem_u32(smem);
    const int tid  = threadIdx.x;
    const int lane = tid & 31;
    const int wid  = tid >> 5;
    const int wm = wid >> 2;
    const int wn = wid & 3;

    if (tid < 128) ((float*)(smem + SM_B1))[tid] = b1[tid];

    // ---- stage B once: B[n][k] = W1[k][n] (n<128) / W1[128+k][n-128] ----
    {
        int n = tid;
        int c = n & 127;
        int rbase = (n < 128) ? 0 : 128;
        #pragma unroll 4
        for (int kc = 0; kc < 32; kc++) {
            float f0 = W1[(size_t)(rbase + kc * 4 + 0) * 128 + c];
            float f1 = W1[(size_t)(rbase + kc * 4 + 1) * 128 + c];
            float f2 = W1[(size_t)(rbase + kc * 4 + 2) * 128 + c];
            float f3 = W1[(size_t)(rbase + kc * 4 + 3) * 128 + c];
            __half2 h01 = __floats2half2_rn(f0, f1);
            __half2 h23 = __floats2half2_rn(f2, f3);
            uint2 v;
            v.x = *(uint32_t*)&h01;
            v.y = *(uint32_t*)&h23;
            uint32_t off = ((uint32_t)(kc * 8)) ^ ((uint32_t)(n & 7) << 4);
            *(uint2*)(smem + SM_B + n * 256 + off) = v;
        }
    }
    __syncthreads();

    float bx[8], by[8];
    #pragma unroll
    for (int nj = 0; nj < 8; nj++) {
        int col = wn * 64 + nj * 8 + ((lane & 3) << 1);
        if (col < 128) {
            float2 bb = *(const float2*)(smem + SM_B1 + col * 4);
            bx[nj] = bb.x; by[nj] = bb.y;
        } else {
            bx[nj] = 0.f; by[nj] = 0.f;
        }
    }

    const uint32_t smA = smem_base + SM_A;
    const uint32_t smB = smem_base + SM_B;

    for (int tile = blockIdx.x; tile < n_tiles; tile += gridDim.x) {
        const int node0 = tile * NODES_PER_CTA;

        #pragma unroll
        for (int i = 0; i < 8; i++) {
            int chunk = tid + i * 256;
            int row = chunk >> 5, c4 = chunk & 31;
            int gn = node0 + row;
            float4 f = make_float4(0.f, 0.f, 0.f, 0.f);
            if (gn < n_nodes) f = ((const float4*)(z + (size_t)gn * HIDDEN))[c4];
            __half2 h01 = __floats2half2_rn(f.x, f.y);
            __half2 h23 = __floats2half2_rn(f.z, f.w);
            uint2 v;
            v.x = *(uint32_t*)&h01;
            v.y = *(uint32_t*)&h23;
            uint32_t off = ((uint32_t)(c4 * 8)) ^ ((uint32_t)(row & 7) << 4);
            *(uint2*)(smem + SM_A + row * 256 + off) = v;
        }
        __syncthreads();

        float acc[2][8][4];
        #pragma unroll
        for (int mi = 0; mi < 2; mi++)
            #pragma unroll
            for (int nj = 0; nj < 8; nj++)
                #pragma unroll
                for (int q = 0; q < 4; q++) acc[mi][nj][q] = 0.0f;

        #pragma unroll
        for (int ks = 0; ks < 8; ks++) {
            uint32_t a[2][4];
            #pragma unroll
            for (int mi = 0; mi < 2; mi++) {
                int r = wm * 32 + mi * 16 + (lane & 15);
                uint32_t kb = (uint32_t)(ks * 32 + ((lane >> 4) << 4));
                uint32_t addr = smA + (uint32_t)(r * 256) + (kb ^ ((uint32_t)(r & 7) << 4));
                asm volatile("ldmatrix.sync.aligned.m8n8.x4.shared.b16 {%0,%1,%2,%3}, [%4];"
                             : "=r"(a[mi][0]), "=r"(a[mi][1]), "=r"(a[mi][2]), "=r"(a[mi][3])
                             : "r"(addr));
            }
            uint32_t b[8][2];
            #pragma unroll
            for (int nj = 0; nj < 8; nj++) {
                int r = wn * 64 + nj * 8 + (lane & 7);
                uint32_t kb = (uint32_t)(ks * 32 + (((lane >> 3) & 1) << 4));
                uint32_t addr = smB + (uint32_t)(r * 256) + (kb ^ ((uint32_t)(r & 7) << 4));
                asm volatile("ldmatrix.sync.aligned.m8n8.x2.shared.b16 {%0,%1}, [%2];"
                             : "=r"(b[nj][0]), "=r"(b[nj][1]) : "r"(addr));
            }
            #pragma unroll
            for (int mi = 0; mi < 2; mi++)
                #pragma unroll
                for (int nj = 0; nj < 8; nj++) {
                    asm volatile(
                        "mma.sync.aligned.m16n8k16.row.col.f32.f16.f16.f32 "
                        "{%0,%1,%2,%3}, {%4,%5,%6,%7}, {%8,%9}, {%0,%1,%2,%3};"
                        : "+f"(acc[mi][nj][0]), "+f"(acc[mi][nj][1]),
                          "+f"(acc[mi][nj][2]), "+f"(acc[mi][nj][3])
                        : "r"(a[mi][0]), "r"(a[mi][1]), "r"(a[mi][2]), "r"(a[mi][3]),
                          "r"(b[nj][0]), "r"(b[nj][1]));
                }
        }
        __syncthreads();

        #pragma unroll
        for (int mi = 0; mi < 2; mi++) {
            int row = wm * 32 + mi * 16 + (lane >> 2);
            int gn0 = node0 + row;
            int gn1 = gn0 + 8;
            #pragma unroll
            for (int nj = 0; nj < 8; nj++) {
                int col = wn * 64 + nj * 8 + ((lane & 3) << 1);
                __half2 v0 = __floats2half2_rn(acc[mi][nj][0] + bx[nj],
                                               acc[mi][nj][1] + by[nj]);
                __half2 v1 = __floats2half2_rn(acc[mi][nj][2] + bx[nj],
                                               acc[mi][nj][3] + by[nj]);
                if (gn0 < n_nodes) *(__half2*)(g_p + (size_t)gn0 * 256 + col) = v0;
                if (gn1 < n_nodes) *(__half2*)(g_p + (size_t)gn1 * 256 + col) = v1;
            }
        }
    }
}

// ---------------------------------------------------------------------------
// Phase 2: FOUR edges per warp; each half-warp owns 2 edges.
// All 4 gathers (uint4) issued back-to-back for max MLP, then fp16
// add+relu, fp32 dot, 4-stage half-warp butterfly over 2 accumulators.
// ---------------------------------------------------------------------------
__global__ void __launch_bounds__(256) edge_kernel(
    const int* __restrict__ ei,
    const float* __restrict__ W2,
    const float* __restrict__ b2,
    float* __restrict__ out,
    int n_edges)
{
    int warp = (int)((blockIdx.x * (unsigned)blockDim.x + threadIdx.x) >> 5);
    int lane = threadIdx.x & 31;
    int ebase = warp * 4;
    if (ebase >= n_edges) return;

    int half = lane >> 4;       // 0/1: which edge pair
    int kl   = lane & 15;       // k-lane within half-warp

    int e0 = ebase + half * 2;
    int e1 = e0 + 1;
    int c0 = (e0 < n_edges) ? e0 : ebase;
    int c1 = (e1 < n_edges) ? e1 : ebase;

    int s0 = ei[c0], d0 = ei[n_edges + c0];
    int s1 = ei[c1], d1 = ei[n_edges + c1];

    // 4 independent 16B gathers in flight per lane.
    const uint4 ra0 = *(const uint4*)(g_p + (size_t)s0 * 256 + kl * 8);
    const uint4 rb0 = *(const uint4*)(g_p + (size_t)d0 * 256 + 128 + kl * 8);
    const uint4 ra1 = *(const uint4*)(g_p + (size_t)s1 * 256 + kl * 8);
    const uint4 rb1 = *(const uint4*)(g_p + (size_t)d1 * 256 + 128 + kl * 8);

    const float4 w0 = *((const float4*)W2 + kl * 2);
    const float4 w1 = *((const float4*)W2 + kl * 2 + 1);
    const __half2 z2 = __float2half2_rn(0.0f);

    float acc0, acc1;
    {
        __half2 h0 = __hmax2(__hadd2(*(const __half2*)&ra0.x, *(const __half2*)&rb0.x), z2);
        __half2 h1 = __hmax2(__hadd2(*(const __half2*)&ra0.y, *(const __half2*)&rb0.y), z2);
        __half2 h2 = __hmax2(__hadd2(*(const __half2*)&ra0.z, *(const __half2*)&rb0.z), z2);
        __half2 h3 = __hmax2(__hadd2(*(const __half2*)&ra0.w, *(const __half2*)&rb0.w), z2);
        float2 f0 = __half22float2(h0), f1 = __half22float2(h1);
        float2 f2 = __half22float2(h2), f3 = __half22float2(h3);
        acc0 =       f0.x * w0.x;
        acc0 = fmaf(f0.y, w0.y, acc0);
        acc0 = fmaf(f1.x, w0.z, acc0);
        acc0 = fmaf(f1.y, w0.w, acc0);
        acc0 = fmaf(f2.x, w1.x, acc0);
        acc0 = fmaf(f2.y, w1.y, acc0);
        acc0 = fmaf(f3.x, w1.z, acc0);
        acc0 = fmaf(f3.y, w1.w, acc0);
    }
    {
        __half2 h0 = __hmax2(__hadd2(*(const __half2*)&ra1.x, *(const __half2*)&rb1.x), z2);
        __half2 h1 = __hmax2(__hadd2(*(const __half2*)&ra1.y, *(const __half2*)&rb1.y), z2);
        __half2 h2 = __hmax2(__hadd2(*(const __half2*)&ra1.z, *(const __half2*)&rb1.z), z2);
        __half2 h3 = __hmax2(__hadd2(*(const __half2*)&ra1.w, *(const __half2*)&rb1.w), z2);
        float2 f0 = __half22float2(h0), f1 = __half22float2(h1);
        float2 f2 = __half22float2(h2), f3 = __half22float2(h3);
        acc1 =       f0.x * w0.x;
        acc1 = fmaf(f0.y, w0.y, acc1);
        acc1 = fmaf(f1.x, w0.z, acc1);
        acc1 = fmaf(f1.y, w0.w, acc1);
        acc1 = fmaf(f2.x, w1.x, acc1);
        acc1 = fmaf(f2.y, w1.y, acc1);
        acc1 = fmaf(f3.x, w1.z, acc1);
        acc1 = fmaf(f3.y, w1.w, acc1);
    }

    #pragma unroll
    for (int o = 8; o > 0; o >>= 1) {
        acc0 += __shfl_xor_sync(0xFFFFFFFFu, acc0, o);
        acc1 += __shfl_xor_sync(0xFFFFFFFFu, acc1, o);
    }

    if (kl == 0) {
        float bb = b2[0];
        if (e0 < n_edges) out[e0] = acc0 + bb;
        if (e1 < n_edges) out[e1] = acc1 + bb;
    }
}

// ---------------------------------------------------------------------------
// Launch
// ---------------------------------------------------------------------------
extern "C" void kernel_launch(void* const* d_in, const int* in_sizes, int n_in,
                              void* d_out, int out_size)
{
    const float* z  = (const float*)d_in[0];
    const int*   ei = (const int*)d_in[1];
    const float* W1 = (const float*)d_in[2];
    const float* b1 = (const float*)d_in[3];
    const float* W2 = (const float*)d_in[4];
    const float* b2 = (const float*)d_in[5];
    float*       out = (float*)d_out;

    int n_nodes = in_sizes[0] / HIDDEN;
    int n_edges = in_sizes[1] / 2;
    int n_tiles = (n_nodes + NODES_PER_CTA - 1) / NODES_PER_CTA;

    cudaFuncSetAttribute(proj_mma_kernel,
                         cudaFuncAttributeMaxDynamicSharedMemorySize, SMEM_BYTES);

    int pg = 2 * 148;
    if (pg > n_tiles) pg = n_tiles;
    proj_mma_kernel<<<pg, PROJ_THREADS, SMEM_BYTES>>>(z, W1, b1, n_nodes, n_tiles);

    int eb = (n_edges + 31) / 32;     // 32 edges per 256-thread block
    edge_kernel<<<eb, 256>>>(ei, W2, b2, out, n_edges);
}

// round 8
// speedup vs baseline: 3.5633x; 1.1200x over previous
#include <cuda_runtime.h>
#include <cuda_fp16.h>
#include <cstdint>

#define HIDDEN 128
#define MAX_NODES 100000
#define NODES_PER_CTA 64
#define PROJ_THREADS 256

// Interleaved per-node projections, fp16, COLUMN-PERMUTED for dense stores:
// row = [src-proj(+b1) perm | dst-proj perm]. Permutation compensated by g_w2p.
__device__ __half g_p[(size_t)MAX_NODES * 256];
__device__ float  g_w2p[128];     // W2 permuted to stored order

__device__ __forceinline__ uint32_t smem_u32(const void* p) {
    uint32_t a;
    asm("{ .reg .u64 t; cvta.to.shared.u64 t, %1; cvt.u32.u64 %0, t; }"
        : "=r"(a) : "l"(p));
    return a;
}

// Stored-order s (within a 64-half wn-block) -> original column in block.
//   s = (nj>=4)*32 + q*8 + (nj&3)*2 + t   <=>   orig = nj*8 + q*2 + t
__device__ __forceinline__ int perm_orig_in_block(int s) {
    int nj = ((s >> 1) & 3) + ((s >> 5) << 2);
    int q  = (s >> 3) & 3;
    int t  = s & 1;
    return nj * 8 + q * 2 + t;
}

// SMEM layout (dynamic, 82432 B -> 2 CTAs/SM):
//   [0,512)        b1 (128 f32)
//   [512,16896)    A: z fp16, 64 rows x 256B, XOR-16B swizzle   (per tile)
//   [16896,82432)  B: W1^T fp16, 256 rows x 256B, XOR-16B swizzle (persistent)
#define SM_B1  0
#define SM_A   512
#define SM_B   16896
#define SMEM_BYTES 82432

// ---------------------------------------------------------------------------
// Phase 1: persistent-CTA fp16 tensor-core projection.
// Epilogue: packed uint4 stores in permuted column order (sector-dense).
// ---------------------------------------------------------------------------
__global__ void __launch_bounds__(PROJ_THREADS, 2)
proj_mma_kernel(const float* __restrict__ z,
                const float* __restrict__ W1,
                const float* __restrict__ b1,
                const float* __restrict__ W2,
                int n_nodes, int n_tiles)
{
    extern __shared__ char smem[];
    const uint32_t smem_base = smem_u32(smem);
    const int tid  = threadIdx.x;
    const int lane = tid & 31;
    const int wid  = tid >> 5;
    const int wm = wid >> 2;
    const int wn = wid & 3;

    if (tid < 128) ((float*)(smem + SM_B1))[tid] = b1[tid];

    // Write permuted W2 once (edge_kernel runs after proj completes).
    if (blockIdx.x == 0 && tid < 128) {
        int blk = tid >> 6, s = tid & 63;
        g_w2p[tid] = W2[blk * 64 + perm_orig_in_block(s)];
    }

    // ---- stage B once: B[n][k] = W1[k][n] (n<128) / W1[128+k][n-128] ----
    {
        int n = tid;
        int c = n & 127;
        int rbase = (n < 128) ? 0 : 128;
        #pragma unroll 4
        for (int kc = 0; kc < 32; kc++) {
            float f0 = W1[(size_t)(rbase + kc * 4 + 0) * 128 + c];
            float f1 = W1[(size_t)(rbase + kc * 4 + 1) * 128 + c];
            float f2 = W1[(size_t)(rbase + kc * 4 + 2) * 128 + c];
            float f3 = W1[(size_t)(rbase + kc * 4 + 3) * 128 + c];
            __half2 h01 = __floats2half2_rn(f0, f1);
            __half2 h23 = __floats2half2_rn(f2, f3);
            uint2 v;
            v.x = *(uint32_t*)&h01;
            v.y = *(uint32_t*)&h23;
            uint32_t off = ((uint32_t)(kc * 8)) ^ ((uint32_t)(n & 7) << 4);
            *(uint2*)(smem + SM_B + n * 256 + off) = v;
        }
    }
    __syncthreads();

    float bx[8], by[8];
    #pragma unroll
    for (int nj = 0; nj < 8; nj++) {
        int col = wn * 64 + nj * 8 + ((lane & 3) << 1);
        if (col < 128) {
            float2 bb = *(const float2*)(smem + SM_B1 + col * 4);
            bx[nj] = bb.x; by[nj] = bb.y;
        } else {
            bx[nj] = 0.f; by[nj] = 0.f;
        }
    }

    const uint32_t smA = smem_base + SM_A;
    const uint32_t smB = smem_base + SM_B;

    for (int tile = blockIdx.x; tile < n_tiles; tile += gridDim.x) {
        const int node0 = tile * NODES_PER_CTA;

        #pragma unroll
        for (int i = 0; i < 8; i++) {
            int chunk = tid + i * 256;
            int row = chunk >> 5, c4 = chunk & 31;
            int gn = node0 + row;
            float4 f = make_float4(0.f, 0.f, 0.f, 0.f);
            if (gn < n_nodes) f = ((const float4*)(z + (size_t)gn * HIDDEN))[c4];
            __half2 h01 = __floats2half2_rn(f.x, f.y);
            __half2 h23 = __floats2half2_rn(f.z, f.w);
            uint2 v;
            v.x = *(uint32_t*)&h01;
            v.y = *(uint32_t*)&h23;
            uint32_t off = ((uint32_t)(c4 * 8)) ^ ((uint32_t)(row & 7) << 4);
            *(uint2*)(smem + SM_A + row * 256 + off) = v;
        }
        __syncthreads();

        float acc[2][8][4];
        #pragma unroll
        for (int mi = 0; mi < 2; mi++)
            #pragma unroll
            for (int nj = 0; nj < 8; nj++)
                #pragma unroll
                for (int q = 0; q < 4; q++) acc[mi][nj][q] = 0.0f;

        #pragma unroll
        for (int ks = 0; ks < 8; ks++) {
            uint32_t a[2][4];
            #pragma unroll
            for (int mi = 0; mi < 2; mi++) {
                int r = wm * 32 + mi * 16 + (lane & 15);
                uint32_t kb = (uint32_t)(ks * 32 + ((lane >> 4) << 4));
                uint32_t addr = smA + (uint32_t)(r * 256) + (kb ^ ((uint32_t)(r & 7) << 4));
                asm volatile("ldmatrix.sync.aligned.m8n8.x4.shared.b16 {%0,%1,%2,%3}, [%4];"
                             : "=r"(a[mi][0]), "=r"(a[mi][1]), "=r"(a[mi][2]), "=r"(a[mi][3])
                             : "r"(addr));
            }
            uint32_t b[8][2];
            #pragma unroll
            for (int nj = 0; nj < 8; nj++) {
                int r = wn * 64 + nj * 8 + (lane & 7);
                uint32_t kb = (uint32_t)(ks * 32 + (((lane >> 3) & 1) << 4));
                uint32_t addr = smB + (uint32_t)(r * 256) + (kb ^ ((uint32_t)(r & 7) << 4));
                asm volatile("ldmatrix.sync.aligned.m8n8.x2.shared.b16 {%0,%1}, [%2];"
                             : "=r"(b[nj][0]), "=r"(b[nj][1]) : "r"(addr));
            }
            #pragma unroll
            for (int mi = 0; mi < 2; mi++)
                #pragma unroll
                for (int nj = 0; nj < 8; nj++) {
                    asm volatile(
                        "mma.sync.aligned.m16n8k16.row.col.f32.f16.f16.f32 "
                        "{%0,%1,%2,%3}, {%4,%5,%6,%7}, {%8,%9}, {%0,%1,%2,%3};"
                        : "+f"(acc[mi][nj][0]), "+f"(acc[mi][nj][1]),
                          "+f"(acc[mi][nj][2]), "+f"(acc[mi][nj][3])
                        : "r"(a[mi][0]), "r"(a[mi][1]), "r"(a[mi][2]), "r"(a[mi][3]),
                          "r"(b[nj][0]), "r"(b[nj][1]));
                }
        }
        __syncthreads();

        // ---- epilogue: +bias, fp16, packed permuted stores ----
        // Thread owns columns (wn-block, q=lane&3); stored at:
        //   lo (nj0..3): half-offset wn*64 + q*8       (16B)
        //   hi (nj4..7): half-offset wn*64 + 32 + q*8  (16B)
        {
            const int q = lane & 3;
            #pragma unroll
            for (int mi = 0; mi < 2; mi++) {
                int row = wm * 32 + mi * 16 + (lane >> 2);
                int gn0 = node0 + row;
                int gn1 = gn0 + 8;
                uint32_t lo0[4], hi0[4], lo1[4], hi1[4];
                #pragma unroll
                for (int nj = 0; nj < 8; nj++) {
                    __half2 v0 = __floats2half2_rn(acc[mi][nj][0] + bx[nj],
                                                   acc[mi][nj][1] + by[nj]);
                    __half2 v1 = __floats2half2_rn(acc[mi][nj][2] + bx[nj],
                                                   acc[mi][nj][3] + by[nj]);
                    if (nj < 4) { lo0[nj] = *(uint32_t*)&v0; lo1[nj] = *(uint32_t*)&v1; }
                    else        { hi0[nj - 4] = *(uint32_t*)&v0; hi1[nj - 4] = *(uint32_t*)&v1; }
                }
                size_t base0 = (size_t)gn0 * 256 + wn * 64 + q * 8;
                size_t base1 = (size_t)gn1 * 256 + wn * 64 + q * 8;
                if (gn0 < n_nodes) {
                    *(uint4*)(g_p + base0)      = *(uint4*)lo0;
                    *(uint4*)(g_p + base0 + 32) = *(uint4*)hi0;
                }
                if (gn1 < n_nodes) {
                    *(uint4*)(g_p + base1)      = *(uint4*)lo1;
                    *(uint4*)(g_p + base1 + 32) = *(uint4*)hi1;
                }
            }
        }
    }
}

// ---------------------------------------------------------------------------
// Phase 2: EIGHT edges per warp; each half-warp owns 4 edges.
// 8 independent uint4 gathers in flight per lane; edge indices via one int4
// broadcast per half-warp; W2 (permuted) loaded once per warp; float4 output.
// ---------------------------------------------------------------------------
__global__ void __launch_bounds__(256) edge_kernel(
    const int* __restrict__ ei,
    const float* __restrict__ b2,
    float* __restrict__ out,
    int n_edges)
{
    int warp = (int)((blockIdx.x * (unsigned)blockDim.x + threadIdx.x) >> 5);
    int lane = threadIdx.x & 31;
    int ebase = warp * 8;
    if (ebase >= n_edges) return;

    int half = lane >> 4;         // 0/1
    int kl   = lane & 15;
    int e0 = ebase + half * 4;    // this half-warp's first edge

    int sv[4], dv[4];
    bool fast = (ebase + 8 <= n_edges) && ((n_edges & 3) == 0);
    if (fast) {
        int4 s4 = *(const int4*)(ei + e0);
        int4 d4 = *(const int4*)(ei + n_edges + e0);
        sv[0] = s4.x; sv[1] = s4.y; sv[2] = s4.z; sv[3] = s4.w;
        dv[0] = d4.x; dv[1] = d4.y; dv[2] = d4.z; dv[3] = d4.w;
    } else {
        #pragma unroll
        for (int j = 0; j < 4; j++) {
            int c = e0 + j; if (c >= n_edges) c = n_edges - 1;
            sv[j] = ei[c]; dv[j] = ei[n_edges + c];
        }
    }

    // 8 independent 16B gathers.
    uint4 ra[4], rb[4];
    #pragma unroll
    for (int j = 0; j < 4; j++)
        ra[j] = *(const uint4*)(g_p + (size_t)sv[j] * 256 + kl * 8);
    #pragma unroll
    for (int j = 0; j < 4; j++)
        rb[j] = *(const uint4*)(g_p + (size_t)dv[j] * 256 + 128 + kl * 8);

    const float4 w0 = *((const float4*)g_w2p + kl * 2);
    const float4 w1 = *((const float4*)g_w2p + kl * 2 + 1);
    const __half2 z2 = __float2half2_rn(0.0f);

    float accv[4];
    #pragma unroll
    for (int j = 0; j < 4; j++) {
        __half2 h0 = __hmax2(__hadd2(*(const __half2*)&ra[j].x, *(const __half2*)&rb[j].x), z2);
        __half2 h1 = __hmax2(__hadd2(*(const __half2*)&ra[j].y, *(const __half2*)&rb[j].y), z2);
        __half2 h2 = __hmax2(__hadd2(*(const __half2*)&ra[j].z, *(const __half2*)&rb[j].z), z2);
        __half2 h3 = __hmax2(__hadd2(*(const __half2*)&ra[j].w, *(const __half2*)&rb[j].w), z2);
        float2 f0 = __half22float2(h0), f1 = __half22float2(h1);
        float2 f2 = __half22float2(h2), f3 = __half22float2(h3);
        float a =       f0.x * w0.x;
        a = fmaf(f0.y, w0.y, a);
        a = fmaf(f1.x, w0.z, a);
        a = fmaf(f1.y, w0.w, a);
        a = fmaf(f2.x, w1.x, a);
        a = fmaf(f2.y, w1.y, a);
        a = fmaf(f3.x, w1.z, a);
        a = fmaf(f3.y, w1.w, a);
        accv[j] = a;
    }

    #pragma unroll
    for (int o = 8; o > 0; o >>= 1) {
        accv[0] += __shfl_xor_sync(0xFFFFFFFFu, accv[0], o);
        accv[1] += __shfl_xor_sync(0xFFFFFFFFu, accv[1], o);
        accv[2] += __shfl_xor_sync(0xFFFFFFFFu, accv[2], o);
        accv[3] += __shfl_xor_sync(0xFFFFFFFFu, accv[3], o);
    }

    if (kl == 0) {
        float bb = b2[0];
        if (e0 + 4 <= n_edges) {
            float4 o4 = make_float4(accv[0] + bb, accv[1] + bb,
                                    accv[2] + bb, accv[3] + bb);
            *(float4*)(out + e0) = o4;
        } else {
            #pragma unroll
            for (int j = 0; j < 4; j++)
                if (e0 + j < n_edges) out[e0 + j] = accv[j] + bb;
        }
    }
}

// ---------------------------------------------------------------------------
// Launch
// Inputs: 0 z[f32 N*128], 1 edge_index[i32 2*E], 2 W1[f32 256*128],
//         3 b1[f32 128], 4 W2[f32 128], 5 b2[f32 1]; out f32 [E].
// ---------------------------------------------------------------------------
extern "C" void kernel_launch(void* const* d_in, const int* in_sizes, int n_in,
                              void* d_out, int out_size)
{
    const float* z  = (const float*)d_in[0];
    const int*   ei = (const int*)d_in[1];
    const float* W1 = (const float*)d_in[2];
    const float* b1 = (const float*)d_in[3];
    const float* W2 = (const float*)d_in[4];
    const float* b2 = (const float*)d_in[5];
    float*       out = (float*)d_out;

    int n_nodes = in_sizes[0] / HIDDEN;
    int n_edges = in_sizes[1] / 2;
    int n_tiles = (n_nodes + NODES_PER_CTA - 1) / NODES_PER_CTA;

    cudaFuncSetAttribute(proj_mma_kernel,
                         cudaFuncAttributeMaxDynamicSharedMemorySize, SMEM_BYTES);

    int pg = 2 * 148;
    if (pg > n_tiles) pg = n_tiles;
    proj_mma_kernel<<<pg, PROJ_THREADS, SMEM_BYTES>>>(z, W1, b1, W2, n_nodes, n_tiles);

    int eb = (n_edges + 63) / 64;     // 64 edges per 256-thread block
    edge_kernel<<<eb, 256>>>(ei, b2, out, n_edges);
}